// round 2
// baseline (speedup 1.0000x reference)
#include <cuda_runtime.h>
#include <cstdint>

#define DIM 128
#define DIM4 (DIM / 4)   // 32 float4 per row -> one warp lane each

// ---------------------------------------------------------------------------
// Kernel 1: out[i] = (1 + eps) * node_feat[i]   (vectorized float4)
// ---------------------------------------------------------------------------
__global__ void gine_init_kernel(const float* __restrict__ node_feat,
                                 const float* __restrict__ eps,
                                 float* __restrict__ out,
                                 int total4) {
    int i = blockIdx.x * blockDim.x + threadIdx.x;
    if (i >= total4) return;
    float s = 1.0f + eps[0];
    float4 v = reinterpret_cast<const float4*>(node_feat)[i];
    v.x *= s; v.y *= s; v.z *= s; v.w *= s;
    reinterpret_cast<float4*>(out)[i] = v;
}

// ---------------------------------------------------------------------------
// Kernel 2: per edge e: msg = relu(node_feat[src[e]] + edge_feat[e])
//           out[dst[e]] += msg   via red.global.add.v4.f32 (128-bit reduction)
// One warp per edge; lane l handles float4 chunk l (D=128 -> 32 chunks).
// edge_index arrives as int32 (JAX x64-disabled downcasts the int64 request).
// ---------------------------------------------------------------------------
__global__ __launch_bounds__(256, 8)
void gine_edge_kernel(const float* __restrict__ node_feat,
                      const int* __restrict__ edge_index,
                      const float* __restrict__ edge_feat,
                      float* __restrict__ out,
                      int num_edges) {
    int warp_global = (blockIdx.x * blockDim.x + threadIdx.x) >> 5;
    int lane = threadIdx.x & 31;
    if (warp_global >= num_edges) return;

    // edge_index layout: [2, E] row-major int32: row0 = src, row1 = dst
    int src = __ldg(&edge_index[warp_global]);
    int dst = __ldg(&edge_index[num_edges + warp_global]);

    const float4* nf = reinterpret_cast<const float4*>(node_feat + (long long)src * DIM);
    const float4* ef = reinterpret_cast<const float4*>(edge_feat + (long long)warp_global * DIM);

    float4 a = __ldg(&nf[lane]);   // L2-resident gather (25.6MB node table)
    float4 b = ef[lane];           // coalesced streaming read

    float4 m;
    m.x = fmaxf(a.x + b.x, 0.0f);
    m.y = fmaxf(a.y + b.y, 0.0f);
    m.z = fmaxf(a.z + b.z, 0.0f);
    m.w = fmaxf(a.w + b.w, 0.0f);

    float* dptr = out + (long long)dst * DIM + lane * 4;
    // 128-bit vector reduction, no return value (REDG path) — 4x fewer L2
    // atomic transactions than scalar atomicAdd.
    asm volatile("red.global.add.v4.f32 [%0], {%1, %2, %3, %4};"
                 :: "l"(dptr), "f"(m.x), "f"(m.y), "f"(m.z), "f"(m.w)
                 : "memory");
}

// ---------------------------------------------------------------------------
// Launch
// inputs (metadata order): node_feat (N*D f32), edge_index (2*E i32),
//                          edge_feat (E*D f32), eps (1 f32)
// output: (N, D) float32
// ---------------------------------------------------------------------------
extern "C" void kernel_launch(void* const* d_in, const int* in_sizes, int n_in,
                              void* d_out, int out_size) {
    const float* node_feat = (const float*)d_in[0];
    const int* edge_index = (const int*)d_in[1];
    const float* edge_feat = (const float*)d_in[2];
    const float* eps = (const float*)d_in[3];
    float* out = (float*)d_out;

    int N = in_sizes[0] / DIM;
    int E = in_sizes[1] / 2;

    // Phase 1: out = (1 + eps) * node_feat
    int total4 = N * DIM4;
    {
        int threads = 256;
        int blocks = (total4 + threads - 1) / threads;
        gine_init_kernel<<<blocks, threads>>>(node_feat, eps, out, total4);
    }

    // Phase 2: edge scatter (one warp per edge)
    {
        int threads = 256;                 // 8 warps / block
        long long total_threads = (long long)E * 32;
        int blocks = (int)((total_threads + threads - 1) / threads);
        gine_edge_kernel<<<blocks, threads>>>(node_feat, edge_index, edge_feat,
                                              out, E);
    }
}

// round 4
// speedup vs baseline: 1.1157x; 1.1157x over previous
#include <cuda_runtime.h>
#include <cstdint>

#define DIM 128
#define DIM4 (DIM / 4)   // 32 float4 per row -> one warp lane each

// ---------------------------------------------------------------------------
// Kernel 1: out[i] = (1 + eps) * node_feat[i]   (vectorized float4)
// ---------------------------------------------------------------------------
__global__ void gine_init_kernel(const float* __restrict__ node_feat,
                                 const float* __restrict__ eps,
                                 float* __restrict__ out,
                                 int total4) {
    int i = blockIdx.x * blockDim.x + threadIdx.x;
    if (i >= total4) return;
    float s = 1.0f + eps[0];
    float4 v = reinterpret_cast<const float4*>(node_feat)[i];
    v.x *= s; v.y *= s; v.z *= s; v.w *= s;
    reinterpret_cast<float4*>(out)[i] = v;
}

// ---------------------------------------------------------------------------
// Kernel 2: per edge e: msg = relu(node_feat[src[e]] + edge_feat[e])
//           out[dst[e]] += msg   via red.global.add.v4.f32
// One warp per edge; lane l handles float4 chunk l.
// Cache policy:
//   edge_feat / edge_index : ld.global.cs            (streamed once, evict first)
//   node_feat gather       : L2 evict_last via createpolicy + cache_hint
//                            (pin the 25.6MB node table in the 126MB L2)
// ---------------------------------------------------------------------------
__global__ __launch_bounds__(256, 8)
void gine_edge_kernel(const float* __restrict__ node_feat,
                      const int* __restrict__ edge_index,
                      const float* __restrict__ edge_feat,
                      float* __restrict__ out,
                      int num_edges) {
    int warp_global = (blockIdx.x * blockDim.x + threadIdx.x) >> 5;
    int lane = threadIdx.x & 31;
    if (warp_global >= num_edges) return;

    // L2 evict-last policy for the node_feat table
    unsigned long long pol;
    asm volatile("createpolicy.fractional.L2::evict_last.b64 %0, 1.0;"
                 : "=l"(pol));

    // edge_index layout: [2, E] int32: row0 = src, row1 = dst. Streamed once.
    int src, dst;
    asm volatile("ld.global.cs.b32 %0, [%1];" : "=r"(src)
                 : "l"(edge_index + warp_global));
    asm volatile("ld.global.cs.b32 %0, [%1];" : "=r"(dst)
                 : "l"(edge_index + num_edges + warp_global));

    const float* nf = node_feat + (long long)src * DIM + lane * 4;
    const float* ef = edge_feat + (long long)warp_global * DIM + lane * 4;

    // node_feat gather: keep resident in L2 (evict_last policy)
    float4 a;
    asm volatile("ld.global.nc.L2::cache_hint.v4.f32 {%0, %1, %2, %3}, [%4], %5;"
                 : "=f"(a.x), "=f"(a.y), "=f"(a.z), "=f"(a.w)
                 : "l"(nf), "l"(pol));

    // edge_feat: streaming read, evict first (don't pollute L2)
    float4 b;
    asm volatile("ld.global.cs.v4.f32 {%0, %1, %2, %3}, [%4];"
                 : "=f"(b.x), "=f"(b.y), "=f"(b.z), "=f"(b.w) : "l"(ef));

    float4 m;
    m.x = fmaxf(a.x + b.x, 0.0f);
    m.y = fmaxf(a.y + b.y, 0.0f);
    m.z = fmaxf(a.z + b.z, 0.0f);
    m.w = fmaxf(a.w + b.w, 0.0f);

    float* dptr = out + (long long)dst * DIM + lane * 4;
    // 128-bit vector reduction, no return value (REDG path).
    asm volatile("red.global.add.v4.f32 [%0], {%1, %2, %3, %4};"
                 :: "l"(dptr), "f"(m.x), "f"(m.y), "f"(m.z), "f"(m.w)
                 : "memory");
}

// ---------------------------------------------------------------------------
// Launch
// inputs (metadata order): node_feat (N*D f32), edge_index (2*E i32),
//                          edge_feat (E*D f32), eps (1 f32)
// output: (N, D) float32
// ---------------------------------------------------------------------------
extern "C" void kernel_launch(void* const* d_in, const int* in_sizes, int n_in,
                              void* d_out, int out_size) {
    const float* node_feat = (const float*)d_in[0];
    const int* edge_index = (const int*)d_in[1];
    const float* edge_feat = (const float*)d_in[2];
    const float* eps = (const float*)d_in[3];
    float* out = (float*)d_out;

    int N = in_sizes[0] / DIM;
    int E = in_sizes[1] / 2;

    // Phase 1: out = (1 + eps) * node_feat
    int total4 = N * DIM4;
    {
        int threads = 256;
        int blocks = (total4 + threads - 1) / threads;
        gine_init_kernel<<<blocks, threads>>>(node_feat, eps, out, total4);
    }

    // Phase 2: edge scatter (one warp per edge)
    {
        int threads = 256;                 // 8 warps / block
        long long total_threads = (long long)E * 32;
        int blocks = (int)((total_threads + threads - 1) / threads);
        gine_edge_kernel<<<blocks, threads>>>(node_feat, edge_index, edge_feat,
                                              out, E);
    }
}